// round 10
// baseline (speedup 1.0000x reference)
#include <cuda_runtime.h>
#include <cstdint>
#include <cstddef>

#define TT 256
#define BB 64
#define DD 512
#define HH 1024
#define GG 4096
#define NBLK 128
#define EPSB 1e-5f
#define HROW 144   // words per staged k-row (dup h, skewed): max 139, padded

// ---------------- scratch (device globals: no allocation allowed) ----------------
__device__ float g_xw[(size_t)TT * BB * GG];   // 256 MB: raw x@w_ih
__device__ float g_y0[(size_t)TT * BB * HH];   // 64 MB: layer-0 output
__device__ float g_h[2][BB * HH];              // ping-pong hidden state
__device__ int   g_bar[TT];                    // grid barrier counters

// ---------------- packed f32x2 + fast-math helpers ----------------
__device__ __forceinline__ void fma2(unsigned long long& d, unsigned long long a, unsigned long long b) {
    asm("fma.rn.f32x2 %0, %1, %2, %3;" : "=l"(d) : "l"(a), "l"(b), "l"(d));
}
__device__ __forceinline__ float2 upk2(unsigned long long v) {
    float lo, hi;
    asm("mov.b64 {%0, %1}, %2;" : "=f"(lo), "=f"(hi) : "l"(v));
    return make_float2(lo, hi);
}
__device__ __forceinline__ float tanh_f(float x) {
    float r;
    asm("tanh.approx.f32 %0, %1;" : "=f"(r) : "f"(x));
    return r;
}
__device__ __forceinline__ float sigf(float x) { return fmaf(tanh_f(0.5f * x), 0.5f, 0.5f); }

// ---------------- input GEMM: g_xw(raw) = A(16384 x K) @ W(K x 4096) ----------------
__global__ __launch_bounds__(256) void gemm_xw_kernel(const float* __restrict__ A,
                                                      const float* __restrict__ W, int K) {
    __shared__ __align__(16) float As[2][8][132];
    __shared__ __align__(16) float Bd[2][8][260];
    const int n0 = blockIdx.x * 128, m0 = blockIdx.y * 128;
    const int tid = threadIdx.x;
    const int rg = tid & 15, cg = tid >> 4;
    const int r0 = rg * 8, c0 = cg * 8;
    const int ar = tid >> 1, ak = (tid & 1) * 4;
    const int bk = tid >> 5, bc = (tid & 31) * 4;
    const float* pA = A + (size_t)(m0 + ar) * K + ak;
    const float* pB = W + (size_t)bk * GG + n0 + bc;

    unsigned long long acc[4][8] = {};

    float4 va = *(const float4*)pA;
    float4 vb = *(const float4*)pB;
    As[0][ak + 0][ar] = va.x; As[0][ak + 1][ar] = va.y;
    As[0][ak + 2][ar] = va.z; As[0][ak + 3][ar] = va.w;
    *(float2*)&Bd[0][bk][2 * (bc + 0)] = make_float2(vb.x, vb.x);
    *(float2*)&Bd[0][bk][2 * (bc + 1)] = make_float2(vb.y, vb.y);
    *(float2*)&Bd[0][bk][2 * (bc + 2)] = make_float2(vb.z, vb.z);
    *(float2*)&Bd[0][bk][2 * (bc + 3)] = make_float2(vb.w, vb.w);
    __syncthreads();

    int buf = 0;
    for (int kc = 8; kc <= K; kc += 8) {
        const bool more = (kc < K);
        if (more) {
            va = *(const float4*)(pA + kc);
            vb = *(const float4*)(pB + (size_t)kc * GG);
        }
#pragma unroll
        for (int k = 0; k < 8; k++) {
            ulonglong2 a0 = *(const ulonglong2*)&As[buf][k][r0];
            ulonglong2 a1 = *(const ulonglong2*)&As[buf][k][r0 + 4];
            ulonglong2 w01 = *(const ulonglong2*)&Bd[buf][k][2 * c0];
            ulonglong2 w23 = *(const ulonglong2*)&Bd[buf][k][2 * c0 + 4];
            ulonglong2 w45 = *(const ulonglong2*)&Bd[buf][k][2 * c0 + 8];
            ulonglong2 w67 = *(const ulonglong2*)&Bd[buf][k][2 * c0 + 12];
            unsigned long long avp[4] = {a0.x, a0.y, a1.x, a1.y};
            unsigned long long wr[8] = {w01.x, w01.y, w23.x, w23.y, w45.x, w45.y, w67.x, w67.y};
#pragma unroll
            for (int p = 0; p < 4; p++)
#pragma unroll
                for (int c = 0; c < 8; c++) fma2(acc[p][c], avp[p], wr[c]);
        }
        if (more) {
            int nb = buf ^ 1;
            As[nb][ak + 0][ar] = va.x; As[nb][ak + 1][ar] = va.y;
            As[nb][ak + 2][ar] = va.z; As[nb][ak + 3][ar] = va.w;
            *(float2*)&Bd[nb][bk][2 * (bc + 0)] = make_float2(vb.x, vb.x);
            *(float2*)&Bd[nb][bk][2 * (bc + 1)] = make_float2(vb.y, vb.y);
            *(float2*)&Bd[nb][bk][2 * (bc + 2)] = make_float2(vb.z, vb.z);
            *(float2*)&Bd[nb][bk][2 * (bc + 3)] = make_float2(vb.w, vb.w);
            __syncthreads();
            buf = nb;
        }
    }
#pragma unroll
    for (int p = 0; p < 4; p++) {
        float2 u[8];
#pragma unroll
        for (int c = 0; c < 8; c++) u[c] = upk2(acc[p][c]);
        float* o0 = &g_xw[(size_t)(m0 + r0 + 2 * p) * GG + n0 + c0];
        float* o1 = o0 + GG;
        *(float4*)o0       = make_float4(u[0].x, u[1].x, u[2].x, u[3].x);
        *(float4*)(o0 + 4) = make_float4(u[4].x, u[5].x, u[6].x, u[7].x);
        *(float4*)o1       = make_float4(u[0].y, u[1].y, u[2].y, u[3].y);
        *(float4*)(o1 + 4) = make_float4(u[4].y, u[5].y, u[6].y, u[7].y);
    }
}

// ---------------- init: zero h ping-pong + barrier counters ----------------
__global__ void init_kernel() {
    const int i = blockIdx.x * 256 + threadIdx.x;
    if (i < 2 * BB * HH) ((float*)g_h)[i] = 0.f;
    if (i < TT) g_bar[i] = 0;
}

// ---------------- epilogue smem layout (aliases the h staging region) ----------------
struct SR {
    float Cs[2][64][34];
    float Xs[64][36];
    float redA[8][32], redB[8][32], redC[8][32], redD[8][32];
    float scH[32], shH[32], scX[32], shX[32];
    float c1s[64][9], oss[64][9];
    float scc[8], shc[8];
};

// skewed dup-h word index for batch row b (conflict-free LDS.128 reads)
__device__ __forceinline__ int hword(int b) {
    return 8 * (b >> 2) + 4 * (b >> 4) + 2 * (b & 3);
}

// ---------------- persistent recurrence kernel: all 256 steps of one layer ----------------
// 128 blocks x 256 threads, 1 block/SM (smem-bound) -> all co-resident, atomic grid barrier.
// Block blk owns gate cols {g*1024 + blk*8 + j}. Weights live in smem for the whole kernel.
__global__ __launch_bounds__(256) void lstm_persist_kernel(
    const float* __restrict__ whh,
    const float* __restrict__ ghh, const float* __restrict__ bthh,
    const float* __restrict__ gih, const float* __restrict__ btih,
    const float* __restrict__ bias,
    const float* __restrict__ gcb, const float* __restrict__ btcb,
    const int* __restrict__ length,
    float* __restrict__ y_out, float* __restrict__ hn_out, float* __restrict__ cn_out) {
    extern __shared__ float smem[];
    float* wsm = smem;                                       // [1024][32]
    float (*hst)[32][HROW] = (float (*)[32][HROW])(smem + HH * 32);
    SR* sr = (SR*)(smem + HH * 32);

    const int blk = blockIdx.x, tid = threadIdx.x;

    // ---- one-time: load this block's 32 weight cols (1024x32 = 128 KB) ----
    for (int idx = tid; idx < HH * 32; idx += 256) {
        int c = idx & 31, k = idx >> 5;
        wsm[k * 32 + c] = whh[(size_t)k * GG + (c >> 3) * HH + blk * 8 + (c & 7)];
    }

    // ---- per-thread element mapping (epilogue): f = tid*2+i -> b = f>>3, j = f&7 ----
    float cr[2] = {0.f, 0.f}, hr[2] = {0.f, 0.f};
    int lenr[2];
#pragma unroll
    for (int i = 0; i < 2; i++) lenr[i] = length[(tid * 2 + i) >> 3];

    // GEMM lane mapping: quarter q (2 warps) does k%... its 8 k's of each 32-chunk
    const int q = tid >> 6, tq = tid & 63;
    const int rg = tq & 15, cg = tq >> 4;
    const int RB = 8 * rg + 4 * (rg >> 2);       // dup-h read base (skewed)

    __syncthreads();

    for (int t = 0; t < TT; t++) {
        const int par = t & 1;
        const float* hin = g_h[par];
        float* hout = g_h[par ^ 1];

        // ---- prefetch xw slice (consumed ~10us later in the epilogue) ----
        float4 xwv[2];
#pragma unroll
        for (int i = 0; i < 2; i++) {
            int f = tid * 2 + i;
            int b = f >> 3, sub = f & 7;
            int gate = sub >> 1, jj = (sub & 1) * 4;
            xwv[i] = __ldg((const float4*)&g_xw[((size_t)t * BB + b) * GG + gate * HH + blk * 8 + jj]);
        }

        // ---- GEMM: C(64x32) = hin(64x1024) @ wsm(1024x32), K-split 4, chunked 32 ----
        unsigned long long acc[4][4] = {};

        float4 sh[2];
#pragma unroll
        for (int i = 0; i < 2; i++) {
            int u = tid * 2 + i;
            int sb = u >> 3, kq = (u & 7) * 4;
            sh[i] = __ldcv((const float4*)&hin[sb * HH + kq]);
        }
#pragma unroll
        for (int i = 0; i < 2; i++) {
            int u = tid * 2 + i;
            int sb = u >> 3, kq = (u & 7) * 4;
            int w = hword(sb);
            *(float2*)&hst[0][kq + 0][w] = make_float2(sh[i].x, sh[i].x);
            *(float2*)&hst[0][kq + 1][w] = make_float2(sh[i].y, sh[i].y);
            *(float2*)&hst[0][kq + 2][w] = make_float2(sh[i].z, sh[i].z);
            *(float2*)&hst[0][kq + 3][w] = make_float2(sh[i].w, sh[i].w);
        }
        __syncthreads();

        int buf = 0;
        for (int kc = 32; kc <= HH; kc += 32) {
            const bool more = (kc < HH);
            if (more) {
#pragma unroll
                for (int i = 0; i < 2; i++) {
                    int u = tid * 2 + i;
                    int sb = u >> 3, kq = (u & 7) * 4;
                    sh[i] = __ldcv((const float4*)&hin[sb * HH + kc + kq]);
                }
            }
            const int kbase = kc - 32;
#pragma unroll
            for (int kk = 0; kk < 8; kk++) {
                int k = q * 8 + kk;
                ulonglong2 a01 = *(const ulonglong2*)&hst[buf][k][RB];
                ulonglong2 a23 = *(const ulonglong2*)&hst[buf][k][RB + 4];
                const float* wr_ = &wsm[(kbase + k) * 32 + 8 * cg];
                ulonglong2 wlo = *(const ulonglong2*)wr_;
                ulonglong2 whi = *(const ulonglong2*)(wr_ + 4);
                unsigned long long av[4] = {a01.x, a01.y, a23.x, a23.y};
                unsigned long long wv[4] = {wlo.x, wlo.y, whi.x, whi.y};
#pragma unroll
                for (int r = 0; r < 4; r++)
#pragma unroll
                    for (int cp = 0; cp < 4; cp++) fma2(acc[r][cp], av[r], wv[cp]);
            }
            if (more) {
                int nb = buf ^ 1;
#pragma unroll
                for (int i = 0; i < 2; i++) {
                    int u = tid * 2 + i;
                    int sb = u >> 3, kq = (u & 7) * 4;
                    int w = hword(sb);
                    *(float2*)&hst[nb][kq + 0][w] = make_float2(sh[i].x, sh[i].x);
                    *(float2*)&hst[nb][kq + 1][w] = make_float2(sh[i].y, sh[i].y);
                    *(float2*)&hst[nb][kq + 2][w] = make_float2(sh[i].z, sh[i].z);
                    *(float2*)&hst[nb][kq + 3][w] = make_float2(sh[i].w, sh[i].w);
                }
                __syncthreads();
                buf = nb;
            }
        }
        __syncthreads();   // GEMM reads done; smem aliases to SR below

        // ---- phase 1: quarters 0/1 store partials; everyone stores Xs ----
        if (q < 2) {
#pragma unroll
            for (int r = 0; r < 4; r++)
#pragma unroll
                for (int cp = 0; cp < 4; cp++) {
                    float2 u = upk2(acc[r][cp]);
                    *(float2*)&sr->Cs[q][4 * rg + r][8 * cg + 2 * cp] = u;
                }
        }
#pragma unroll
        for (int i = 0; i < 2; i++) {
            int f = tid * 2 + i;
            int b = f >> 3, sub = f & 7;
            int gate = sub >> 1, jj = (sub & 1) * 4;
            *(float4*)&sr->Xs[b][gate * 8 + jj] = xwv[i];
        }
        __syncthreads();

        // ---- phase 2: quarters 2/3 add their partials ----
        if (q >= 2) {
#pragma unroll
            for (int r = 0; r < 4; r++)
#pragma unroll
                for (int cp = 0; cp < 4; cp++) {
                    float2 u = upk2(acc[r][cp]);
                    float2* p = (float2*)&sr->Cs[q - 2][4 * rg + r][8 * cg + 2 * cp];
                    float2 o = *p;
                    *p = make_float2(o.x + u.x, o.y + u.y);
                }
        }
        __syncthreads();

        // ---- BN stats over batch for hh-GEMM and ih (raw xw) columns ----
        {
            int c = tid & 31, grp = tid >> 5;
            float sC = 0.f, s2C = 0.f, sX = 0.f, s2X = 0.f;
#pragma unroll
            for (int b = grp * 8; b < grp * 8 + 8; b++) {
                float v = sr->Cs[0][b][c] + sr->Cs[1][b][c];
                sr->Cs[0][b][c] = v;
                sC += v; s2C += v * v;
                float u = sr->Xs[b][c];
                sX += u; s2X += u * u;
            }
            sr->redA[grp][c] = sC; sr->redB[grp][c] = s2C;
            sr->redC[grp][c] = sX; sr->redD[grp][c] = s2X;
        }
        __syncthreads();
        if (tid < 32) {
            float sC = 0.f, s2C = 0.f, sX = 0.f, s2X = 0.f;
#pragma unroll
            for (int g = 0; g < 8; g++) {
                sC += sr->redA[g][tid]; s2C += sr->redB[g][tid];
                sX += sr->redC[g][tid]; s2X += sr->redD[g][tid];
            }
            int col = (tid >> 3) * HH + blk * 8 + (tid & 7);
            float muC = sC * (1.f / 64.f);
            float varC = fmaxf(s2C * (1.f / 64.f) - muC * muC, 0.f);
            float a = ghh[col] * rsqrtf(varC + EPSB);
            sr->scH[tid] = a; sr->shH[tid] = bthh[col] - muC * a;
            float muX = sX * (1.f / 64.f);
            float varX = fmaxf(s2X * (1.f / 64.f) - muX * muX, 0.f);
            float e = gih[col] * rsqrtf(varX + EPSB);
            sr->scX[tid] = e; sr->shX[tid] = btih[col] + bias[col] - muX * e;
        }
        __syncthreads();

        // ---- gates + cell update (c from registers) ----
#pragma unroll
        for (int i = 0; i < 2; i++) {
            int f = tid * 2 + i;
            int b = f >> 3, j = f & 7;
            float pre[4];
#pragma unroll
            for (int g = 0; g < 4; g++) {
                int c = g * 8 + j;
                pre[g] = sr->Cs[0][b][c] * sr->scH[c] + sr->shH[c]
                       + sr->Xs[b][c] * sr->scX[c] + sr->shX[c];
            }
            float c1 = sigf(pre[0]) * cr[i] + sigf(pre[1]) * tanh_f(pre[3]);
            sr->c1s[b][j] = c1;
            sr->oss[b][j] = sigf(pre[2]);
        }
        __syncthreads();

        // ---- BN stats over batch for the 8 cell columns ----
        if (tid < 64) {
            int j = tid & 7, grp = tid >> 3;
            float s = 0.f, s2 = 0.f;
#pragma unroll
            for (int b = grp * 8; b < grp * 8 + 8; b++) {
                float v = sr->c1s[b][j]; s += v; s2 += v * v;
            }
            sr->redA[grp][j] = s; sr->redB[grp][j] = s2;
        }
        __syncthreads();
        if (tid < 8) {
            float s = 0.f, s2 = 0.f;
#pragma unroll
            for (int g = 0; g < 8; g++) { s += sr->redA[g][tid]; s2 += sr->redB[g][tid]; }
            float mu = s * (1.f / 64.f);
            float var = fmaxf(s2 * (1.f / 64.f) - mu * mu, 0.f);
            int hcol = blk * 8 + tid;
            float a = gcb[hcol] * rsqrtf(var + EPSB);
            sr->scc[tid] = a; sr->shc[tid] = btcb[hcol] - mu * a;
        }
        __syncthreads();

        // ---- h update with length mask; write h, y (and final h/c at t=TT-1) ----
#pragma unroll
        for (int i = 0; i < 2; i++) {
            int f = tid * 2 + i;
            int b = f >> 3, j = f & 7;
            int hcol = blk * 8 + j;
            float c1 = sr->c1s[b][j];
            float h1 = sr->oss[b][j] * tanh_f(c1 * sr->scc[j] + sr->shc[j]);
            bool m = t < lenr[i];
            float hn = m ? h1 : hr[i];
            float cn = m ? c1 : cr[i];
            hr[i] = hn; cr[i] = cn;
            hout[b * HH + hcol] = hn;
            y_out[((size_t)t * BB + b) * HH + hcol] = hn;
            if (t == TT - 1) {
                hn_out[b * HH + hcol] = hn;
                cn_out[b * HH + hcol] = cn;
            }
        }

        // ---- grid barrier: release writes, arrive, spin, acquire ----
        __threadfence();
        __syncthreads();
        if (tid == 0) {
            atomicAdd(&g_bar[t], 1);
            while (((volatile int*)g_bar)[t] < NBLK) { __nanosleep(64); }
        }
        __syncthreads();
    }
}

// ---------------- host orchestration ----------------
extern "C" void kernel_launch(void* const* d_in, const int* in_sizes, int n_in,
                              void* d_out, int out_size) {
    const float* x     = (const float*)d_in[0];
    const int* length  = (const int*)d_in[1];
    const float* w_ih0 = (const float*)d_in[2];
    const float* w_hh0 = (const float*)d_in[3];
    const float* b0    = (const float*)d_in[4];
    const float* gih0  = (const float*)d_in[5];
    const float* btih0 = (const float*)d_in[6];
    const float* ghh0  = (const float*)d_in[7];
    const float* bthh0 = (const float*)d_in[8];
    const float* gc0   = (const float*)d_in[9];
    const float* btc0  = (const float*)d_in[10];
    const float* w_ih1 = (const float*)d_in[11];
    const float* w_hh1 = (const float*)d_in[12];
    const float* b1    = (const float*)d_in[13];
    const float* gih1  = (const float*)d_in[14];
    const float* btih1 = (const float*)d_in[15];
    const float* ghh1  = (const float*)d_in[16];
    const float* bthh1 = (const float*)d_in[17];
    const float* gc1   = (const float*)d_in[18];
    const float* btc1  = (const float*)d_in[19];

    float* out = (float*)d_out;
    float* y1 = out;
    float* hn = out + (size_t)TT * BB * HH;
    float* cn = hn + 2 * BB * HH;

    float* p_y0 = nullptr;
    cudaGetSymbolAddress((void**)&p_y0, g_y0);

    // dynamic smem: 128 KB weights + max(h staging, SR) region
    const size_t smreg = (size_t)2 * 32 * HROW * sizeof(float);   // 36864
    const size_t srsz = sizeof(SR);
    const size_t smbytes = (size_t)HH * 32 * sizeof(float) + (smreg > srsz ? smreg : srsz);
    cudaFuncSetAttribute(lstm_persist_kernel,
                         cudaFuncAttributeMaxDynamicSharedMemorySize, (int)smbytes);

    const dim3 ggrid(GG / 128, (TT * BB) / 128);
    const int initgrid = (2 * BB * HH + 255) / 256;

    // ---- layer 0 ----
    gemm_xw_kernel<<<ggrid, 256>>>(x, w_ih0, DD);
    init_kernel<<<initgrid, 256>>>();
    lstm_persist_kernel<<<NBLK, 256, smbytes>>>(w_hh0, ghh0, bthh0, gih0, btih0, b0,
                                                gc0, btc0, length, p_y0, hn, cn);

    // ---- layer 1 ----
    gemm_xw_kernel<<<ggrid, 256>>>(p_y0, w_ih1, HH);
    init_kernel<<<initgrid, 256>>>();
    lstm_persist_kernel<<<NBLK, 256, smbytes>>>(w_hh1, ghh1, bthh1, gih1, btih1, b1,
                                                gc1, btc1, length, y1, hn + BB * HH, cn + BB * HH);
}

// round 12
// speedup vs baseline: 1.6432x; 1.6432x over previous
#include <cuda_runtime.h>
#include <cstdint>
#include <cstddef>

#define TT 256
#define BB 64
#define DD 512
#define HH 1024
#define GG 4096
#define NBLK 128
#define EPSB 1e-5f
#define HROW 144   // words per staged k-row; MUST be %4==0 (16B-aligned rows for LDS.128)

// ---------------- scratch (device globals: no allocation allowed) ----------------
__device__ float g_xw[(size_t)TT * BB * GG];   // 256 MB: raw x@w_ih
__device__ float g_y0[(size_t)TT * BB * HH];   // 64 MB: layer-0 output (h history for layer 0)
__device__ float g_hzero[BB * HH];             // zeros (t=0 h source)
__device__ int   g_flag[NBLK * 32];            // per-producer progress flags, 128B stride

// ---------------- packed f32x2 + fast-math helpers ----------------
__device__ __forceinline__ void fma2(unsigned long long& d, unsigned long long a, unsigned long long b) {
    asm("fma.rn.f32x2 %0, %1, %2, %3;" : "=l"(d) : "l"(a), "l"(b), "l"(d));
}
__device__ __forceinline__ float2 upk2(unsigned long long v) {
    float lo, hi;
    asm("mov.b64 {%0, %1}, %2;" : "=f"(lo), "=f"(hi) : "l"(v));
    return make_float2(lo, hi);
}
__device__ __forceinline__ float tanh_f(float x) {
    float r;
    asm("tanh.approx.f32 %0, %1;" : "=f"(r) : "f"(x));
    return r;
}
__device__ __forceinline__ float sigf(float x) { return fmaf(tanh_f(0.5f * x), 0.5f, 0.5f); }
__device__ __forceinline__ int ldacq(const int* p) {
    int v;
    asm volatile("ld.acquire.gpu.global.b32 %0, [%1];" : "=r"(v) : "l"(p) : "memory");
    return v;
}

// ---------------- input GEMM: g_xw(raw) = A(16384 x K) @ W(K x 4096) ----------------
__global__ __launch_bounds__(256) void gemm_xw_kernel(const float* __restrict__ A,
                                                      const float* __restrict__ W, int K) {
    __shared__ __align__(16) float As[2][8][132];
    __shared__ __align__(16) float Bd[2][8][260];
    const int n0 = blockIdx.x * 128, m0 = blockIdx.y * 128;
    const int tid = threadIdx.x;
    const int rg = tid & 15, cg = tid >> 4;
    const int r0 = rg * 8, c0 = cg * 8;
    const int ar = tid >> 1, ak = (tid & 1) * 4;
    const int bk = tid >> 5, bc = (tid & 31) * 4;
    const float* pA = A + (size_t)(m0 + ar) * K + ak;
    const float* pB = W + (size_t)bk * GG + n0 + bc;

    unsigned long long acc[4][8] = {};

    float4 va = *(const float4*)pA;
    float4 vb = *(const float4*)pB;
    As[0][ak + 0][ar] = va.x; As[0][ak + 1][ar] = va.y;
    As[0][ak + 2][ar] = va.z; As[0][ak + 3][ar] = va.w;
    *(float2*)&Bd[0][bk][2 * (bc + 0)] = make_float2(vb.x, vb.x);
    *(float2*)&Bd[0][bk][2 * (bc + 1)] = make_float2(vb.y, vb.y);
    *(float2*)&Bd[0][bk][2 * (bc + 2)] = make_float2(vb.z, vb.z);
    *(float2*)&Bd[0][bk][2 * (bc + 3)] = make_float2(vb.w, vb.w);
    __syncthreads();

    int buf = 0;
    for (int kc = 8; kc <= K; kc += 8) {
        const bool more = (kc < K);
        if (more) {
            va = *(const float4*)(pA + kc);
            vb = *(const float4*)(pB + (size_t)kc * GG);
        }
#pragma unroll
        for (int k = 0; k < 8; k++) {
            ulonglong2 a0 = *(const ulonglong2*)&As[buf][k][r0];
            ulonglong2 a1 = *(const ulonglong2*)&As[buf][k][r0 + 4];
            ulonglong2 w01 = *(const ulonglong2*)&Bd[buf][k][2 * c0];
            ulonglong2 w23 = *(const ulonglong2*)&Bd[buf][k][2 * c0 + 4];
            ulonglong2 w45 = *(const ulonglong2*)&Bd[buf][k][2 * c0 + 8];
            ulonglong2 w67 = *(const ulonglong2*)&Bd[buf][k][2 * c0 + 12];
            unsigned long long avp[4] = {a0.x, a0.y, a1.x, a1.y};
            unsigned long long wr[8] = {w01.x, w01.y, w23.x, w23.y, w45.x, w45.y, w67.x, w67.y};
#pragma unroll
            for (int p = 0; p < 4; p++)
#pragma unroll
                for (int c = 0; c < 8; c++) fma2(acc[p][c], avp[p], wr[c]);
        }
        if (more) {
            int nb = buf ^ 1;
            As[nb][ak + 0][ar] = va.x; As[nb][ak + 1][ar] = va.y;
            As[nb][ak + 2][ar] = va.z; As[nb][ak + 3][ar] = va.w;
            *(float2*)&Bd[nb][bk][2 * (bc + 0)] = make_float2(vb.x, vb.x);
            *(float2*)&Bd[nb][bk][2 * (bc + 1)] = make_float2(vb.y, vb.y);
            *(float2*)&Bd[nb][bk][2 * (bc + 2)] = make_float2(vb.z, vb.z);
            *(float2*)&Bd[nb][bk][2 * (bc + 3)] = make_float2(vb.w, vb.w);
            __syncthreads();
            buf = nb;
        }
    }
#pragma unroll
    for (int p = 0; p < 4; p++) {
        float2 u[8];
#pragma unroll
        for (int c = 0; c < 8; c++) u[c] = upk2(acc[p][c]);
        float* o0 = &g_xw[(size_t)(m0 + r0 + 2 * p) * GG + n0 + c0];
        float* o1 = o0 + GG;
        *(float4*)o0       = make_float4(u[0].x, u[1].x, u[2].x, u[3].x);
        *(float4*)(o0 + 4) = make_float4(u[4].x, u[5].x, u[6].x, u[7].x);
        *(float4*)o1       = make_float4(u[0].y, u[1].y, u[2].y, u[3].y);
        *(float4*)(o1 + 4) = make_float4(u[4].y, u[5].y, u[6].y, u[7].y);
    }
}

// ---------------- init: zero flag array + zero-h buffer ----------------
__global__ void init_kernel() {
    const int i = blockIdx.x * 256 + threadIdx.x;
    if (i < BB * HH) g_hzero[i] = 0.f;
    if (i < NBLK * 32) g_flag[i] = 0;
}

// ---------------- epilogue smem layout (aliases the h staging region) ----------------
struct SR {
    float Cs[2][64][34];
    float Xs[64][36];
    float redA[8][32], redB[8][32], redC[8][32], redD[8][32];
    float scH[32], shH[32], scX[32], shX[32];
    float c1s[64][9], oss[64][9];
    float scc[8], shc[8];
};

// skewed dup-h word index for batch row b
__device__ __forceinline__ int hword(int b) {
    return 8 * (b >> 2) + 4 * (b >> 4) + 2 * (b & 3);
}

// ---------------- persistent recurrence kernel: all 256 steps of one layer ----------------
// 128 blocks x 256 threads, 1 block/SM (smem-bound). Block blk owns gate cols
// {g*1024 + blk*8 + j}. Weights smem-resident. NO grid barrier: h history lives in
// y_out (y IS the masked h), producers publish per-block progress flags, consumers
// gate each 32-k staging chunk on the producer flags (prefetched one chunk ahead).
__global__ __launch_bounds__(256) void lstm_persist_kernel(
    const float* __restrict__ whh,
    const float* __restrict__ ghh, const float* __restrict__ bthh,
    const float* __restrict__ gih, const float* __restrict__ btih,
    const float* __restrict__ bias,
    const float* __restrict__ gcb, const float* __restrict__ btcb,
    const int* __restrict__ length,
    float* __restrict__ y_out, float* __restrict__ hn_out, float* __restrict__ cn_out) {
    extern __shared__ float smem[];
    float* wsm = smem;                                       // [1024][32]
    float (*hst)[32][HROW] = (float (*)[32][HROW])(smem + HH * 32);
    SR* sr = (SR*)(smem + HH * 32);

    const int blk = blockIdx.x, tid = threadIdx.x;

    // ---- one-time: load this block's 32 weight cols (1024x32 = 128 KB) ----
    for (int idx = tid; idx < HH * 32; idx += 256) {
        int c = idx & 31, k = idx >> 5;
        wsm[k * 32 + c] = whh[(size_t)k * GG + (c >> 3) * HH + blk * 8 + (c & 7)];
    }

    float cr[2] = {0.f, 0.f}, hr[2] = {0.f, 0.f};
    int lenr[2];
#pragma unroll
    for (int i = 0; i < 2; i++) lenr[i] = length[(tid * 2 + i) >> 3];

    // GEMM lane mapping
    const int q = tid >> 6, tq = tid & 63;
    const int rg = tq & 15, cg = tq >> 4;
    const int RB = 8 * rg + 4 * (rg >> 2);

    // staging slot constants: slot i covers h row sb, cols [kc+kq, kc+kq+4)
    const int u0 = tid * 2, u1 = tid * 2 + 1;
    const int sb0 = u0 >> 3, kq0 = (u0 & 7) * 4;
    const int sb1 = u1 >> 3, kq1 = (u1 & 7) * 4;
    const int fq0 = (kq0 >> 3) * 32, fq1 = (kq1 >> 3) * 32;  // flag sub-offset in chunk group

    // initial flag prefetch for chunk 0 of step 0
    int fv0 = __ldcg(&g_flag[fq0]);
    int fv1 = __ldcg(&g_flag[fq1]);

    __syncthreads();

    for (int t = 0; t < TT; t++) {
        const float* hsrc = t ? (y_out + (size_t)(t - 1) * BB * HH) : g_hzero;

        // ---- prefetch xw slice (consumed in the epilogue) ----
        float4 xwv[2];
#pragma unroll
        for (int i = 0; i < 2; i++) {
            int f = tid * 2 + i;
            int b = f >> 3, sub = f & 7;
            int gate = sub >> 1, jj = (sub & 1) * 4;
            xwv[i] = __ldg((const float4*)&g_xw[((size_t)t * BB + b) * GG + gate * HH + blk * 8 + jj]);
        }

        // ---- GEMM: C(64x32) = h(64x1024) @ wsm(1024x32), K-split 4, chunked 32 ----
        unsigned long long acc[4][4] = {};

        // chunk 0: gate on flags (prefetched), load, stage; prefetch flags for chunk 32
        while (fv0 < t) fv0 = ldacq(&g_flag[fq0]);
        while (fv1 < t) fv1 = ldacq(&g_flag[fq1]);
        float4 sh0 = __ldcv((const float4*)&hsrc[sb0 * HH + kq0]);
        float4 sh1 = __ldcv((const float4*)&hsrc[sb1 * HH + kq1]);
        fv0 = __ldcg(&g_flag[128 + fq0]);
        fv1 = __ldcg(&g_flag[128 + fq1]);
        {
            int w = hword(sb0);
            *(float2*)&hst[0][kq0 + 0][w] = make_float2(sh0.x, sh0.x);
            *(float2*)&hst[0][kq0 + 1][w] = make_float2(sh0.y, sh0.y);
            *(float2*)&hst[0][kq0 + 2][w] = make_float2(sh0.z, sh0.z);
            *(float2*)&hst[0][kq0 + 3][w] = make_float2(sh0.w, sh0.w);
            w = hword(sb1);
            *(float2*)&hst[0][kq1 + 0][w] = make_float2(sh1.x, sh1.x);
            *(float2*)&hst[0][kq1 + 1][w] = make_float2(sh1.y, sh1.y);
            *(float2*)&hst[0][kq1 + 2][w] = make_float2(sh1.z, sh1.z);
            *(float2*)&hst[0][kq1 + 3][w] = make_float2(sh1.w, sh1.w);
        }
        __syncthreads();

        int buf = 0;
        for (int kc = 32; kc <= HH; kc += 32) {
            const bool more = (kc < HH);
            if (more) {
                const int gb = (kc >> 3) * 32;
                while (fv0 < t) fv0 = ldacq(&g_flag[gb + fq0]);
                while (fv1 < t) fv1 = ldacq(&g_flag[gb + fq1]);
                sh0 = __ldcv((const float4*)&hsrc[sb0 * HH + kc + kq0]);
                sh1 = __ldcv((const float4*)&hsrc[sb1 * HH + kc + kq1]);
                // prefetch flags for the next staging chunk (wraps to chunk 0 of next step)
                const int nb_ = (kc < HH - 32) ? (gb + 128) : 0;
                fv0 = __ldcg(&g_flag[nb_ + fq0]);
                fv1 = __ldcg(&g_flag[nb_ + fq1]);
            }
            const int kbase = kc - 32;
#pragma unroll
            for (int kk = 0; kk < 8; kk++) {
                int k = q * 8 + kk;
                ulonglong2 a01 = *(const ulonglong2*)&hst[buf][k][RB];
                ulonglong2 a23 = *(const ulonglong2*)&hst[buf][k][RB + 4];
                const float* wr_ = &wsm[(kbase + k) * 32 + 8 * cg];
                ulonglong2 wlo = *(const ulonglong2*)wr_;
                ulonglong2 whi = *(const ulonglong2*)(wr_ + 4);
                unsigned long long av[4] = {a01.x, a01.y, a23.x, a23.y};
                unsigned long long wv[4] = {wlo.x, wlo.y, whi.x, whi.y};
#pragma unroll
                for (int r = 0; r < 4; r++)
#pragma unroll
                    for (int cp = 0; cp < 4; cp++) fma2(acc[r][cp], av[r], wv[cp]);
            }
            if (more) {
                int nb = buf ^ 1;
                int w = hword(sb0);
                *(float2*)&hst[nb][kq0 + 0][w] = make_float2(sh0.x, sh0.x);
                *(float2*)&hst[nb][kq0 + 1][w] = make_float2(sh0.y, sh0.y);
                *(float2*)&hst[nb][kq0 + 2][w] = make_float2(sh0.z, sh0.z);
                *(float2*)&hst[nb][kq0 + 3][w] = make_float2(sh0.w, sh0.w);
                w = hword(sb1);
                *(float2*)&hst[nb][kq1 + 0][w] = make_float2(sh1.x, sh1.x);
                *(float2*)&hst[nb][kq1 + 1][w] = make_float2(sh1.y, sh1.y);
                *(float2*)&hst[nb][kq1 + 2][w] = make_float2(sh1.z, sh1.z);
                *(float2*)&hst[nb][kq1 + 3][w] = make_float2(sh1.w, sh1.w);
                __syncthreads();
                buf = nb;
            }
        }
        __syncthreads();   // GEMM reads done; smem aliases to SR below

        // ---- phase 1: quarters 0/1 store partials; everyone stores Xs ----
        if (q < 2) {
#pragma unroll
            for (int r = 0; r < 4; r++)
#pragma unroll
                for (int cp = 0; cp < 4; cp++) {
                    float2 u = upk2(acc[r][cp]);
                    *(float2*)&sr->Cs[q][4 * rg + r][8 * cg + 2 * cp] = u;
                }
        }
#pragma unroll
        for (int i = 0; i < 2; i++) {
            int f = tid * 2 + i;
            int b = f >> 3, sub = f & 7;
            int gate = sub >> 1, jj = (sub & 1) * 4;
            *(float4*)&sr->Xs[b][gate * 8 + jj] = xwv[i];
        }
        __syncthreads();

        // ---- phase 2: quarters 2/3 add their partials ----
        if (q >= 2) {
#pragma unroll
            for (int r = 0; r < 4; r++)
#pragma unroll
                for (int cp = 0; cp < 4; cp++) {
                    float2 u = upk2(acc[r][cp]);
                    float2* p = (float2*)&sr->Cs[q - 2][4 * rg + r][8 * cg + 2 * cp];
                    float2 o = *p;
                    *p = make_float2(o.x + u.x, o.y + u.y);
                }
        }
        __syncthreads();

        // ---- BN stats over batch for hh-GEMM and ih (raw xw) columns ----
        {
            int c = tid & 31, grp = tid >> 5;
            float sC = 0.f, s2C = 0.f, sX = 0.f, s2X = 0.f;
#pragma unroll
            for (int b = grp * 8; b < grp * 8 + 8; b++) {
                float v = sr->Cs[0][b][c] + sr->Cs[1][b][c];
                sr->Cs[0][b][c] = v;
                sC += v; s2C += v * v;
                float u = sr->Xs[b][c];
                sX += u; s2X += u * u;
            }
            sr->redA[grp][c] = sC; sr->redB[grp][c] = s2C;
            sr->redC[grp][c] = sX; sr->redD[grp][c] = s2X;
        }
        __syncthreads();
        if (tid < 32) {
            float sC = 0.f, s2C = 0.f, sX = 0.f, s2X = 0.f;
#pragma unroll
            for (int g = 0; g < 8; g++) {
                sC += sr->redA[g][tid]; s2C += sr->redB[g][tid];
                sX += sr->redC[g][tid]; s2X += sr->redD[g][tid];
            }
            int col = (tid >> 3) * HH + blk * 8 + (tid & 7);
            float muC = sC * (1.f / 64.f);
            float varC = fmaxf(s2C * (1.f / 64.f) - muC * muC, 0.f);
            float a = ghh[col] * rsqrtf(varC + EPSB);
            sr->scH[tid] = a; sr->shH[tid] = bthh[col] - muC * a;
            float muX = sX * (1.f / 64.f);
            float varX = fmaxf(s2X * (1.f / 64.f) - muX * muX, 0.f);
            float e = gih[col] * rsqrtf(varX + EPSB);
            sr->scX[tid] = e; sr->shX[tid] = btih[col] + bias[col] - muX * e;
        }
        __syncthreads();

        // ---- gates + cell update (c from registers) ----
#pragma unroll
        for (int i = 0; i < 2; i++) {
            int f = tid * 2 + i;
            int b = f >> 3, j = f & 7;
            float pre[4];
#pragma unroll
            for (int g = 0; g < 4; g++) {
                int c = g * 8 + j;
                pre[g] = sr->Cs[0][b][c] * sr->scH[c] + sr->shH[c]
                       + sr->Xs[b][c] * sr->scX[c] + sr->shX[c];
            }
            float c1 = sigf(pre[0]) * cr[i] + sigf(pre[1]) * tanh_f(pre[3]);
            sr->c1s[b][j] = c1;
            sr->oss[b][j] = sigf(pre[2]);
        }
        __syncthreads();

        // ---- BN stats over batch for the 8 cell columns ----
        if (tid < 64) {
            int j = tid & 7, grp = tid >> 3;
            float s = 0.f, s2 = 0.f;
#pragma unroll
            for (int b = grp * 8; b < grp * 8 + 8; b++) {
                float v = sr->c1s[b][j]; s += v; s2 += v * v;
            }
            sr->redA[grp][j] = s; sr->redB[grp][j] = s2;
        }
        __syncthreads();
        if (tid < 8) {
            float s = 0.f, s2 = 0.f;
#pragma unroll
            for (int g = 0; g < 8; g++) { s += sr->redA[g][tid]; s2 += sr->redB[g][tid]; }
            float mu = s * (1.f / 64.f);
            float var = fmaxf(s2 * (1.f / 64.f) - mu * mu, 0.f);
            int hcol = blk * 8 + tid;
            float a = gcb[hcol] * rsqrtf(var + EPSB);
            sr->scc[tid] = a; sr->shc[tid] = btcb[hcol] - mu * a;
        }
        __syncthreads();

        // ---- h update with length mask; write y (= h history) + finals ----
#pragma unroll
        for (int i = 0; i < 2; i++) {
            int f = tid * 2 + i;
            int b = f >> 3, j = f & 7;
            int hcol = blk * 8 + j;
            float c1 = sr->c1s[b][j];
            float h1 = sr->oss[b][j] * tanh_f(c1 * sr->scc[j] + sr->shc[j]);
            bool m = t < lenr[i];
            float hn = m ? h1 : hr[i];
            float cn = m ? c1 : cr[i];
            hr[i] = hn; cr[i] = cn;
            y_out[((size_t)t * BB + b) * HH + hcol] = hn;
            if (t == TT - 1) {
                hn_out[b * HH + hcol] = hn;
                cn_out[b * HH + hcol] = cn;
            }
        }

        // ---- publish progress: writes visible, then release flag ----
        __threadfence();
        __syncthreads();
        if (tid == 0) {
            asm volatile("st.release.gpu.global.b32 [%0], %1;"
                         :: "l"(&g_flag[blk * 32]), "r"(t + 1) : "memory");
        }
    }
}

// ---------------- host orchestration ----------------
extern "C" void kernel_launch(void* const* d_in, const int* in_sizes, int n_in,
                              void* d_out, int out_size) {
    const float* x     = (const float*)d_in[0];
    const int* length  = (const int*)d_in[1];
    const float* w_ih0 = (const float*)d_in[2];
    const float* w_hh0 = (const float*)d_in[3];
    const float* b0    = (const float*)d_in[4];
    const float* gih0  = (const float*)d_in[5];
    const float* btih0 = (const float*)d_in[6];
    const float* ghh0  = (const float*)d_in[7];
    const float* bthh0 = (const float*)d_in[8];
    const float* gc0   = (const float*)d_in[9];
    const float* btc0  = (const float*)d_in[10];
    const float* w_ih1 = (const float*)d_in[11];
    const float* w_hh1 = (const float*)d_in[12];
    const float* b1    = (const float*)d_in[13];
    const float* gih1  = (const float*)d_in[14];
    const float* btih1 = (const float*)d_in[15];
    const float* ghh1  = (const float*)d_in[16];
    const float* bthh1 = (const float*)d_in[17];
    const float* gc1   = (const float*)d_in[18];
    const float* btc1  = (const float*)d_in[19];

    float* out = (float*)d_out;
    float* y1 = out;
    float* hn = out + (size_t)TT * BB * HH;
    float* cn = hn + 2 * BB * HH;

    float* p_y0 = nullptr;
    cudaGetSymbolAddress((void**)&p_y0, g_y0);

    // dynamic smem: 128 KB weights + max(h staging, SR) region
    const size_t smreg = (size_t)2 * 32 * HROW * sizeof(float);
    const size_t srsz = sizeof(SR);
    const size_t smbytes = (size_t)HH * 32 * sizeof(float) + (smreg > srsz ? smreg : srsz);
    cudaFuncSetAttribute(lstm_persist_kernel,
                         cudaFuncAttributeMaxDynamicSharedMemorySize, (int)smbytes);

    const dim3 ggrid(GG / 128, (TT * BB) / 128);
    const int initgrid = (BB * HH + 255) / 256;

    // ---- layer 0 ----
    gemm_xw_kernel<<<ggrid, 256>>>(x, w_ih0, DD);
    init_kernel<<<initgrid, 256>>>();
    lstm_persist_kernel<<<NBLK, 256, smbytes>>>(w_hh0, ghh0, bthh0, gih0, btih0, b0,
                                                gc0, btc0, length, p_y0, hn, cn);

    // ---- layer 1 ----
    gemm_xw_kernel<<<ggrid, 256>>>(p_y0, w_ih1, HH);
    init_kernel<<<initgrid, 256>>>();
    lstm_persist_kernel<<<NBLK, 256, smbytes>>>(w_hh1, ghh1, bthh1, gih1, btih1, b1,
                                                gc1, btc1, length, y1, hn + BB * HH, cn + BB * HH);
}